// round 3
// baseline (speedup 1.0000x reference)
#include <cuda_runtime.h>
#include <math.h>

#define RBM_B 2048
#define RBM_V 4096
#define RBM_H 1024

// Scratch (device globals: allocation-free rule)
static __device__ float g_WT[(size_t)RBM_H * RBM_V];   // 16 MB  W transposed [H,V]
static __device__ float g_h [(size_t)RBM_B * RBM_H];   //  8 MB  current h (binary as float)
static __device__ float g_v [(size_t)RBM_B * RBM_V];   // 32 MB  current v (binary as float)
static __device__ float g_pos[RBM_B * 16];             // pos score partials (16 n-tiles @ N=1024)
static __device__ float g_neg[RBM_B * 64];             // neg score partials (64 n-tiles @ N=4096)

typedef unsigned long long u64;

// packed f32x2 FMA (full-rate fp32 on sm_103a; per-lane rounding identical to scalar FFMA)
__device__ __forceinline__ void ffma2(u64& d, u64 a, u64 b) {
    asm("fma.rn.f32x2 %0, %1, %2, %0;" : "+l"(d) : "l"(a), "l"(b));
}

// ---------------- transpose W[V,H] -> WT[H,V] ----------------
__global__ void k_transpose(const float* __restrict__ W, float* __restrict__ WT) {
    __shared__ float t[32][33];
    int h0 = blockIdx.x * 32, v0 = blockIdx.y * 32;
#pragma unroll
    for (int i = 0; i < 4; ++i)
        t[threadIdx.y + 8*i][threadIdx.x] =
            W[(size_t)(v0 + threadIdx.y + 8*i) * RBM_H + h0 + threadIdx.x];
    __syncthreads();
#pragma unroll
    for (int i = 0; i < 4; ++i)
        WT[(size_t)(h0 + threadIdx.y + 8*i) * RBM_V + v0 + threadIdx.x] =
            t[threadIdx.x][threadIdx.y + 8*i];
}

// ---------------- fused GEMM + bias + sigmoid-Bernoulli sample (+score) ----------------
// C[M,N] = A[M,K] * Bm[K,N]   (Bm row-major [K,N]); A is binary {0,1} (products exact).
// CRITICAL: single accumulator per output element, strict ascending-k FMA chain --
// reproduces the serial-K rounding order of cuBLAS/XLA SIMT SGEMM bit-for-bit.
// out[m,n] = (sigmoid(C+bias[n]) > U[m,n]) ? 1 : 0
// SCORE!=0: Score[m, blockIdx.x] = sum_n_in_tile( out * (C+bias) )
template<int SCORE>
__global__ __launch_bounds__(256, 2)
void k_gemm_sample(const float* __restrict__ A, const float* __restrict__ Bm,
                   const float* __restrict__ bias, const float* __restrict__ U,
                   float* __restrict__ Out, float* __restrict__ Score,
                   int K, int N)
{
    constexpr int BM = 128, BN = 64, BK = 16;
    __shared__ __align__(16) float As[2][BK][BM];       // A transposed tile
    __shared__ __align__(16) float Bs[2][BK][BN * 2];   // B tile, each value duplicated (for f32x2)

    const int tid = threadIdx.x;
    const int tx = tid & 15, ty = tid >> 4;             // 16x16 thread grid; thread tile 8m x 4n
    const int m0 = blockIdx.y * BM, n0 = blockIdx.x * BN;

    const int arow = tid >> 1;                          // A load: row, 8 consecutive k per thread
    const int acol = (tid & 1) * 8;
    const int brow = tid >> 4;                          // B load: row, 4 consecutive n per thread
    const int bcol = (tid & 15) * 4;

    const float* Aload = A + (size_t)(m0 + arow) * K + acol;
    const float* Bload = Bm + (size_t)brow * N + n0 + bcol;

    // single accumulator per element: [m-pair][n]; each u64 = fp32 pair (2 adjacent m rows)
    u64 acc[4][4];
#pragma unroll
    for (int p = 0; p < 4; ++p)
#pragma unroll
        for (int j = 0; j < 4; ++j) acc[p][j] = 0ull;

    float4 pa0, pa1, pb;

    // prologue: tile 0
    pa0 = *(const float4*)(Aload);
    pa1 = *(const float4*)(Aload + 4);
    pb  = *(const float4*)(Bload);
    {
#pragma unroll
        for (int c = 0; c < 4; ++c) As[0][acol + c][arow]     = ((const float*)&pa0)[c];
#pragma unroll
        for (int c = 0; c < 4; ++c) As[0][acol + 4 + c][arow] = ((const float*)&pa1)[c];
        float* bd = &Bs[0][brow][bcol * 2];
        bd[0]=pb.x; bd[1]=pb.x; bd[2]=pb.y; bd[3]=pb.y;
        bd[4]=pb.z; bd[5]=pb.z; bd[6]=pb.w; bd[7]=pb.w;
    }
    __syncthreads();

    const int nk = K / BK;
    int buf = 0;
    for (int t = 0; t < nk; ++t) {
        if (t + 1 < nk) {
            const float* Ap = Aload + (t + 1) * BK;
            pa0 = *(const float4*)(Ap);
            pa1 = *(const float4*)(Ap + 4);
            pb  = *(const float4*)(Bload + (size_t)(t + 1) * BK * N);
        }
        // strict ascending-k serial accumulation (16 independent FFMA2 chains for ILP)
#pragma unroll
        for (int kk = 0; kk < BK; ++kk) {
            const ulonglong2* Au = (const ulonglong2*)&As[buf][kk][0];
            const ulonglong2* Bu = (const ulonglong2*)&Bs[buf][kk][0];
            ulonglong2 A01 = Au[ty * 2], A23 = Au[ty * 2 + 1];
            ulonglong2 B01 = Bu[tx * 2], B23 = Bu[tx * 2 + 1];
            u64 ap[4] = {A01.x, A01.y, A23.x, A23.y};   // m-pairs
            u64 bp[4] = {B01.x, B01.y, B23.x, B23.y};   // duplicated n values
#pragma unroll
            for (int p = 0; p < 4; ++p)
#pragma unroll
                for (int j = 0; j < 4; ++j)
                    ffma2(acc[p][j], ap[p], bp[j]);
        }
        if (t + 1 < nk) {
            int nb = buf ^ 1;
#pragma unroll
            for (int c = 0; c < 4; ++c) As[nb][acol + c][arow]     = ((const float*)&pa0)[c];
#pragma unroll
            for (int c = 0; c < 4; ++c) As[nb][acol + 4 + c][arow] = ((const float*)&pa1)[c];
            float* bd = &Bs[nb][brow][bcol * 2];
            bd[0]=pb.x; bd[1]=pb.x; bd[2]=pb.y; bd[3]=pb.y;
            bd[4]=pb.z; bd[5]=pb.z; bd[6]=pb.w; bd[7]=pb.w;
        }
        __syncthreads();
        buf ^= 1;
    }

    // epilogue: bias + sigmoid + Bernoulli + optional per-row score partial
    const int gnb = n0 + tx * 4;
    const float4 bias4 = *(const float4*)(bias + gnb);
#pragma unroll
    for (int p = 0; p < 4; ++p) {
#pragma unroll
        for (int half = 0; half < 2; ++half) {
            int gm = m0 + ty * 8 + p * 2 + half;
            const float4 u4 = *(const float4*)(U + (size_t)gm * N + gnb);
            float l[4], s[4];
#pragma unroll
            for (int j = 0; j < 4; ++j) {
                float2 a2 = *(float2*)&acc[p][j];
                float c = half ? a2.y : a2.x;
                l[j] = c + ((const float*)&bias4)[j];
                float pr = 1.0f / (1.0f + expf(-l[j]));   // libdevice expf + IEEE div (XLA lowering)
                s[j] = (pr > ((const float*)&u4)[j]) ? 1.0f : 0.0f;
            }
            *(float4*)(Out + (size_t)gm * N + gnb) = make_float4(s[0], s[1], s[2], s[3]);
            if (SCORE) {
                float sp = s[0]*l[0] + s[1]*l[1] + s[2]*l[2] + s[3]*l[3];
#pragma unroll
                for (int off = 8; off; off >>= 1)
                    sp += __shfl_xor_sync(0xffffffffu, sp, off);
                if (tx == 0) Score[(size_t)gm * gridDim.x + blockIdx.x] = sp;
            }
        }
    }
}

// ---------------- finalize: out[b] = (v.b_v + pos) - (neg + h2.b_h) ----------------
__global__ void k_finalize(const float* __restrict__ visible, const float* __restrict__ b_v,
                           const float* __restrict__ b_h, float* __restrict__ out)
{
    int b = blockIdx.x, tid = threadIdx.x;
    float acc = 0.f;
    const float* vr = visible + (size_t)b * RBM_V;
    for (int i = tid; i < RBM_V; i += 256) acc += vr[i] * b_v[i];
    const float* hr = g_h + (size_t)b * RBM_H;            // g_h holds h2 here
    for (int i = tid; i < RBM_H; i += 256) acc -= hr[i] * b_h[i];
    if (tid < 16) acc += g_pos[b * 16 + tid];
    if (tid < 64) acc -= g_neg[b * 64 + tid];
    __shared__ float red[256];
    red[tid] = acc;
    __syncthreads();
    for (int o = 128; o; o >>= 1) { if (tid < o) red[tid] += red[tid + o]; __syncthreads(); }
    if (tid == 0) out[b] = red[0];
}

// ---------------- launch ----------------
extern "C" void kernel_launch(void* const* d_in, const int* in_sizes, int n_in,
                              void* d_out, int out_size)
{
    const float* visible = (const float*)d_in[0];
    const float* b_v     = (const float*)d_in[1];
    const float* b_h     = (const float*)d_in[2];
    const float* W       = (const float*)d_in[3];
    const float* u_h0    = (const float*)d_in[4];
    const float* u_v     = (const float*)d_in[5];
    const float* u_h     = (const float*)d_in[6];
    float* out = (float*)d_out;

    float *WT, *hb, *vb, *pos, *neg;
    cudaGetSymbolAddress((void**)&WT,  g_WT);
    cudaGetSymbolAddress((void**)&hb,  g_h);
    cudaGetSymbolAddress((void**)&vb,  g_v);
    cudaGetSymbolAddress((void**)&pos, g_pos);
    cudaGetSymbolAddress((void**)&neg, g_neg);

    k_transpose<<<dim3(RBM_H / 32, RBM_V / 32), dim3(32, 8)>>>(W, WT);

    dim3 blk(256);
    dim3 gH(RBM_H / 64, RBM_B / 128);   // N = 1024 -> 16 x 16 = 256 CTAs
    dim3 gV(RBM_V / 64, RBM_B / 128);   // N = 4096 -> 64 x 16 = 1024 CTAs

    const size_t BV = (size_t)RBM_B * RBM_V;
    const size_t BH = (size_t)RBM_B * RBM_H;

    // positive phase: h0 | data, fused pos-score
    k_gemm_sample<1><<<gH, blk>>>(visible, W,  b_h, u_h0,        hb, pos,    RBM_V, RBM_H);
    // Gibbs chain: v,h,v,h,v
    k_gemm_sample<0><<<gV, blk>>>(hb,      WT, b_v, u_v + 0*BV,  vb, nullptr, RBM_H, RBM_V);
    k_gemm_sample<0><<<gH, blk>>>(vb,      W,  b_h, u_h + 0*BH,  hb, nullptr, RBM_V, RBM_H);
    k_gemm_sample<0><<<gV, blk>>>(hb,      WT, b_v, u_v + 1*BV,  vb, nullptr, RBM_H, RBM_V);
    k_gemm_sample<0><<<gH, blk>>>(vb,      W,  b_h, u_h + 1*BH,  hb, nullptr, RBM_V, RBM_H);
    // last v-step: fused neg-score (neg = sum_v v3*(b_v+Y3), plus h2.b_h in finalize)
    k_gemm_sample<2><<<gV, blk>>>(hb,      WT, b_v, u_v + 2*BV,  vb, neg,     RBM_H, RBM_V);

    k_finalize<<<RBM_B, 256>>>(visible, b_v, b_h, out);
}

// round 4
// speedup vs baseline: 1.3289x; 1.3289x over previous
#include <cuda_runtime.h>
#include <math.h>

#define RBM_B 2048
#define RBM_V 4096
#define RBM_H 1024

// Scratch (device globals: allocation-free rule)
static __device__ float g_WT[(size_t)RBM_H * RBM_V];   // 16 MB  W transposed [H,V]
static __device__ float g_h [(size_t)RBM_B * RBM_H];   //  8 MB  current h (binary as float)
static __device__ float g_v [(size_t)RBM_B * RBM_V];   // 32 MB  current v (binary as float)
static __device__ float g_pos[RBM_B * 16];             // pos score partials (8 n-tiles used)
static __device__ float g_neg[RBM_B * 64];             // neg score partials (32 n-tiles used)

typedef unsigned long long u64;

// packed f32x2 FMA (full-rate fp32 on sm_103a; per-lane rounding identical to scalar FFMA)
__device__ __forceinline__ void ffma2(u64& d, u64 a, u64 b) {
    asm("fma.rn.f32x2 %0, %1, %2, %0;" : "+l"(d) : "l"(a), "l"(b));
}
__device__ __forceinline__ u64 dup32(float v) {
    unsigned u = __float_as_uint(v);
    return (u64)u | ((u64)u << 32);
}

// ---------------- transpose W[V,H] -> WT[H,V] ----------------
__global__ void k_transpose(const float* __restrict__ W, float* __restrict__ WT) {
    __shared__ float t[32][33];
    int h0 = blockIdx.x * 32, v0 = blockIdx.y * 32;
#pragma unroll
    for (int i = 0; i < 4; ++i)
        t[threadIdx.y + 8*i][threadIdx.x] =
            W[(size_t)(v0 + threadIdx.y + 8*i) * RBM_H + h0 + threadIdx.x];
    __syncthreads();
#pragma unroll
    for (int i = 0; i < 4; ++i)
        WT[(size_t)(h0 + threadIdx.y + 8*i) * RBM_V + v0 + threadIdx.x] =
            t[threadIdx.x][threadIdx.y + 8*i];
}

// ---------------- fused GEMM + bias + sigmoid-Bernoulli sample (+score) ----------------
// C[M,N] = A[M,K] * Bm[K,N]; A binary {0,1} (products exact).
// CRITICAL: single accumulator per output element, strict ascending-k fma.rn.f32x2 chain
// (bit-identical logits to the round-3 passing kernel).
// Thread tile 8m x 8n; CTA = 128 threads, BM=64, BN=128, BK=16, 4 CTAs/SM.
template<int SCORE>
__global__ __launch_bounds__(128, 4)
void k_gemm_sample(const float* __restrict__ A, const float* __restrict__ Bm,
                   const float* __restrict__ bias, const float* __restrict__ U,
                   float* __restrict__ Out, float* __restrict__ Score,
                   int K, int N)
{
    constexpr int BM = 64, BN = 128, BK = 16;
    __shared__ __align__(16) float As[2][BK][BM];        // A transposed tile (8 KB)
    // Bs: duplicated pairs as u64, laid out [kk][j(0..7)][tx(0..15)] so that
    // the inner-loop read Bu[j*16+tx] is a conflict-free broadcast LDS.64.
    __shared__ __align__(16) u64 Bs[2][BK][BN];          // 32 KB

    const int tid = threadIdx.x;
    const int tx = tid & 15, ty = tid >> 4;              // 16 x 8 threads; tile 8m x 8n
    const int m0 = blockIdx.y * BM, n0 = blockIdx.x * BN;

    const int arow = tid >> 1;                           // A: 64 rows, 8 consecutive k each
    const int acol = (tid & 1) * 8;
    const int brow = tid >> 3;                           // B: 16 rows, 16 consecutive n each
    const int bcol = (tid & 7) * 16;

    const float* Aload = A + (size_t)(m0 + arow) * K + acol;
    const float* Bload = Bm + (size_t)brow * N + n0 + bcol;

    // accumulators: [m-pair 0..3][n 0..7]; each u64 = fp32 pair (2 adjacent m rows)
    u64 acc[4][8];
#pragma unroll
    for (int p = 0; p < 4; ++p)
#pragma unroll
        for (int j = 0; j < 8; ++j) acc[p][j] = 0ull;

    float4 pa[2], pb[4];

    // ---- prologue: tile 0 ----
    pa[0] = *(const float4*)(Aload);
    pa[1] = *(const float4*)(Aload + 4);
#pragma unroll
    for (int q = 0; q < 4; ++q) pb[q] = *(const float4*)(Bload + q * 4);
    {
#pragma unroll
        for (int c = 0; c < 8; ++c)
            As[0][acol + c][arow] = ((const float*)&pa[0])[c];   // pa[0..1] contiguous
        u64* bd = &Bs[0][brow][0];
#pragma unroll
        for (int i = 0; i < 16; ++i) {
            float v = ((const float*)&pb[0])[i];
            int nl = bcol + i;                                    // local n
            bd[(nl & 7) * 16 + (nl >> 3)] = dup32(v);
        }
    }
    __syncthreads();

    const int nk = K / BK;
    int buf = 0;
    for (int t = 0; t < nk; ++t) {
        if (t + 1 < nk) {
            const float* Ap = Aload + (t + 1) * BK;
            pa[0] = *(const float4*)(Ap);
            pa[1] = *(const float4*)(Ap + 4);
            const float* Bp = Bload + (size_t)(t + 1) * BK * N;
#pragma unroll
            for (int q = 0; q < 4; ++q) pb[q] = *(const float4*)(Bp + q * 4);
        }
        // strict ascending-k serial accumulation (32 independent FFMA2 chains)
#pragma unroll
        for (int kk = 0; kk < BK; ++kk) {
            const ulonglong2* Au = (const ulonglong2*)&As[buf][kk][0];
            ulonglong2 A01 = Au[ty * 2], A23 = Au[ty * 2 + 1];
            u64 ap[4] = {A01.x, A01.y, A23.x, A23.y};
            const u64* Bu = &Bs[buf][kk][0];
            u64 bp[8];
#pragma unroll
            for (int j = 0; j < 8; ++j) bp[j] = Bu[j * 16 + tx];
#pragma unroll
            for (int p = 0; p < 4; ++p)
#pragma unroll
                for (int j = 0; j < 8; ++j)
                    ffma2(acc[p][j], ap[p], bp[j]);
        }
        if (t + 1 < nk) {
            int nb = buf ^ 1;
#pragma unroll
            for (int c = 0; c < 8; ++c)
                As[nb][acol + c][arow] = ((const float*)&pa[0])[c];
            u64* bd = &Bs[nb][brow][0];
#pragma unroll
            for (int i = 0; i < 16; ++i) {
                float v = ((const float*)&pb[0])[i];
                int nl = bcol + i;
                bd[(nl & 7) * 16 + (nl >> 3)] = dup32(v);
            }
        }
        __syncthreads();
        buf ^= 1;
    }

    // ---- epilogue: bias + sigmoid + Bernoulli + optional per-row score partial ----
    const int gnb = n0 + tx * 8;
    float bias8[8];
    *(float4*)&bias8[0] = *(const float4*)(bias + gnb);
    *(float4*)&bias8[4] = *(const float4*)(bias + gnb + 4);
#pragma unroll
    for (int p = 0; p < 4; ++p) {
#pragma unroll
        for (int half = 0; half < 2; ++half) {
            int gm = m0 + ty * 8 + p * 2 + half;
            float u8[8];
            *(float4*)&u8[0] = *(const float4*)(U + (size_t)gm * N + gnb);
            *(float4*)&u8[4] = *(const float4*)(U + (size_t)gm * N + gnb + 4);
            float l[8], s[8];
#pragma unroll
            for (int j = 0; j < 8; ++j) {
                float2 a2 = *(float2*)&acc[p][j];
                float c = half ? a2.y : a2.x;
                l[j] = c + bias8[j];
                float pr = 1.0f / (1.0f + expf(-l[j]));   // libdevice expf + IEEE div
                s[j] = (pr > u8[j]) ? 1.0f : 0.0f;
            }
            *(float4*)(Out + (size_t)gm * N + gnb)     = make_float4(s[0], s[1], s[2], s[3]);
            *(float4*)(Out + (size_t)gm * N + gnb + 4) = make_float4(s[4], s[5], s[6], s[7]);
            if (SCORE) {
                float sp = 0.f;
#pragma unroll
                for (int j = 0; j < 8; ++j) sp += s[j] * l[j];
#pragma unroll
                for (int off = 8; off; off >>= 1)
                    sp += __shfl_xor_sync(0xffffffffu, sp, off);
                if (tx == 0) Score[(size_t)gm * gridDim.x + blockIdx.x] = sp;
            }
        }
    }
}

// ---------------- finalize: out[b] = (v.b_v + pos) - (neg + h2.b_h) ----------------
__global__ void k_finalize(const float* __restrict__ visible, const float* __restrict__ b_v,
                           const float* __restrict__ b_h, float* __restrict__ out)
{
    int b = blockIdx.x, tid = threadIdx.x;
    float acc = 0.f;
    const float* vr = visible + (size_t)b * RBM_V;
    for (int i = tid; i < RBM_V; i += 256) acc += vr[i] * b_v[i];
    const float* hr = g_h + (size_t)b * RBM_H;            // g_h holds h2 here
    for (int i = tid; i < RBM_H; i += 256) acc -= hr[i] * b_h[i];
    if (tid < 8)  acc += g_pos[b * 8 + tid];              // 8 n-tiles (BN=128, N=1024)
    if (tid < 32) acc -= g_neg[b * 32 + tid];             // 32 n-tiles (BN=128, N=4096)
    __shared__ float red[256];
    red[tid] = acc;
    __syncthreads();
    for (int o = 128; o; o >>= 1) { if (tid < o) red[tid] += red[tid + o]; __syncthreads(); }
    if (tid == 0) out[b] = red[0];
}

// ---------------- launch ----------------
extern "C" void kernel_launch(void* const* d_in, const int* in_sizes, int n_in,
                              void* d_out, int out_size)
{
    const float* visible = (const float*)d_in[0];
    const float* b_v     = (const float*)d_in[1];
    const float* b_h     = (const float*)d_in[2];
    const float* W       = (const float*)d_in[3];
    const float* u_h0    = (const float*)d_in[4];
    const float* u_v     = (const float*)d_in[5];
    const float* u_h     = (const float*)d_in[6];
    float* out = (float*)d_out;

    float *WT, *hb, *vb, *pos, *neg;
    cudaGetSymbolAddress((void**)&WT,  g_WT);
    cudaGetSymbolAddress((void**)&hb,  g_h);
    cudaGetSymbolAddress((void**)&vb,  g_v);
    cudaGetSymbolAddress((void**)&pos, g_pos);
    cudaGetSymbolAddress((void**)&neg, g_neg);

    k_transpose<<<dim3(RBM_H / 32, RBM_V / 32), dim3(32, 8)>>>(W, WT);

    dim3 blk(128);
    dim3 gH(RBM_H / 128, RBM_B / 64);   // (8, 32)  = 256 CTAs
    dim3 gV(RBM_V / 128, RBM_B / 64);   // (32, 32) = 1024 CTAs

    const size_t BV = (size_t)RBM_B * RBM_V;
    const size_t BH = (size_t)RBM_B * RBM_H;

    // positive phase: h0 | data, fused pos-score
    k_gemm_sample<1><<<gH, blk>>>(visible, W,  b_h, u_h0,        hb, pos,    RBM_V, RBM_H);
    // Gibbs chain: v,h,v,h,v
    k_gemm_sample<0><<<gV, blk>>>(hb,      WT, b_v, u_v + 0*BV,  vb, nullptr, RBM_H, RBM_V);
    k_gemm_sample<0><<<gH, blk>>>(vb,      W,  b_h, u_h + 0*BH,  hb, nullptr, RBM_V, RBM_H);
    k_gemm_sample<0><<<gV, blk>>>(hb,      WT, b_v, u_v + 1*BV,  vb, nullptr, RBM_H, RBM_V);
    k_gemm_sample<0><<<gH, blk>>>(vb,      W,  b_h, u_h + 1*BH,  hb, nullptr, RBM_V, RBM_H);
    // last v-step: fused neg-score
    k_gemm_sample<2><<<gV, blk>>>(hb,      WT, b_v, u_v + 2*BV,  vb, neg,     RBM_H, RBM_V);

    k_finalize<<<RBM_B, 256>>>(visible, b_v, b_h, out);
}